// round 7
// baseline (speedup 1.0000x reference)
#include <cuda_runtime.h>

// Problem constants (fixed by the dataset)
#define NTOT 4096
#define FDIM 128
#define HDIM 128
#define NG0  512           // nodes in graph 0 (only block with adjacency)
#define E_TOT 131072

// Role layout within ONE fused grid (producers first, waiters last)
#define XB 64              // xhat blocks: [0, 64)           64 rows each
#define EB 64              // edge blocks: [64, 128)         2048 edges each
#define FB 1024            // fill blocks: [128, 1152)       4096 float4 each (contiguous)
#define BB 64              // B (sparse wmat) blocks: [1152, 1216)
#define F0 32              // first 32 fill blocks cover rows 0..511 exactly
#define BID_E0 (XB)
#define BID_F0 (XB + EB)
#define BID_B0 (XB + EB + FB)
#define GRID   (XB + EB + FB + BB)

// Scratch (__device__ globals; self-cleaning each replay -> deterministic)
__device__ float g_Xhat[NG0 * HDIM];
__device__ float g_partials[XB];
__device__ int   g_A[NG0 * NG0];      // histogram; zeroed by B as it reads
__device__ int   g_list[16384];       // distinct graph-0 cells (<= 16384)
__device__ int   g_nlist;             // reset by finalizer
__device__ int   g_count;             // reset by finalizer
__device__ int   g_done;              // reset by finalizer
__device__ int   g_done_x;            // reset by finalizer
__device__ int   g_done_e;            // reset by finalizer
__device__ int   g_done_f0;           // reset by finalizer

__global__ __launch_bounds__(256) void fused_kernel(const float* __restrict__ x,
                                                    const float* __restrict__ W0,
                                                    const float* __restrict__ b0,
                                                    const int*   __restrict__ ei,
                                                    const float* __restrict__ prob,
                                                    float*       __restrict__ out) {
    __shared__ float ws[HDIM][33];
    __shared__ float xs[64][33];
    __shared__ float warpsum[8];
    __shared__ int   wcount[8];
    __shared__ float s_fro;

    int b   = blockIdx.x;
    int tid = threadIdx.x;

    // ======================== FILL role: [128, 1152) ========================
    if (b >= BID_F0 && b < BID_B0) {
        int f = b - BID_F0;
        float4 z = make_float4(0.f, 0.f, 0.f, 0.f);
        float4* o4 = (float4*)out;
        int base = f * 4096;               // contiguous 256KB chunk per block
        #pragma unroll
        for (int it = 0; it < 16; it++)
            o4[base + it * 256 + tid] = z; // 1024 * 4096 f4 == 4,194,304 total
        if (f < F0) {                      // these cover rows 0..511 of out
            __threadfence();
            __syncthreads();
            if (tid == 0) atomicAdd(&g_done_f0, 1);
        }
        return;
    }

    // ======================== EDGE role: [64, 128) ==========================
    if (b >= BID_E0 && b < BID_F0) {
        int base = (b - BID_E0) * 2048;
        #pragma unroll
        for (int k = 0; k < 8; k++) {
            int e = base + k * 256 + tid;
            int s = ei[e];
            int d = ei[E_TOT + e];
            if ((unsigned)s < NG0 && (unsigned)d < NG0) {
                int aidx = s * NG0 + d;
                int old = atomicAdd(&g_A[aidx], 1);
                if (old == 0) {                       // first toucher: append
                    int slot = atomicAdd(&g_nlist, 1);
                    g_list[slot] = aidx;
                }
            }
        }
        __threadfence();
        __syncthreads();
        if (tid == 0) atomicAdd(&g_done_e, 1);
        return;
    }

    // ======================== XHAT role: [0, 64) ============================
    // 64 rows x 128 cols per block; bit-identical to the validated round-6 code
    if (b < XB) {
        int row0 = b * 64;
        int rg   = tid & 15;        // 16 row groups of 4
        int cg   = tid >> 4;        // 16 col groups (h = cg + 16*j)

        float acc[4][8];
#pragma unroll
        for (int j = 0; j < 8; j++) {
            float bb = b0[cg + 16 * j];
#pragma unroll
            for (int i = 0; i < 4; i++) acc[i][j] = bb;
        }

        for (int kc = 0; kc < FDIM; kc += 32) {
            __syncthreads();
            #pragma unroll
            for (int it = 0; it < 4; it++) {
                int idx = it * 256 + tid;
                int h = idx >> 3, c4 = (idx & 7) * 4;
                float4 v = *(const float4*)&W0[h * FDIM + kc + c4];
                ws[h][c4] = v.x; ws[h][c4 + 1] = v.y; ws[h][c4 + 2] = v.z; ws[h][c4 + 3] = v.w;
            }
            #pragma unroll
            for (int it = 0; it < 2; it++) {
                int idx = it * 256 + tid;
                int r = idx >> 3, c4 = (idx & 7) * 4;
                float4 v = *(const float4*)&x[(row0 + r) * FDIM + kc + c4];
                xs[r][c4] = v.x; xs[r][c4 + 1] = v.y; xs[r][c4 + 2] = v.z; xs[r][c4 + 3] = v.w;
            }
            __syncthreads();
#pragma unroll
            for (int kk = 0; kk < 32; kk++) {
                float a[4], bv[8];
#pragma unroll
                for (int i = 0; i < 4; i++) a[i] = xs[rg * 4 + i][kk];
#pragma unroll
                for (int j = 0; j < 8; j++) bv[j] = ws[cg + 16 * j][kk];
#pragma unroll
                for (int i = 0; i < 4; i++)
#pragma unroll
                    for (int j = 0; j < 8; j++) acc[i][j] += a[i] * bv[j];
            }
        }

        float ss = 0.f;
        bool store = (row0 < NG0);
#pragma unroll
        for (int i = 0; i < 4; i++) {
            int r = row0 + rg * 4 + i;
#pragma unroll
            for (int j = 0; j < 8; j++) {
                float v = acc[i][j];
                ss += v * v;
                if (store) g_Xhat[r * HDIM + cg + 16 * j] = v;
            }
        }

#pragma unroll
        for (int off = 16; off > 0; off >>= 1) ss += __shfl_down_sync(0xffffffffu, ss, off);
        if ((tid & 31) == 0) warpsum[tid >> 5] = ss;
        __syncthreads();
        if (tid == 0) {
            float s = 0.f;
            for (int w = 0; w < 8; w++) s += warpsum[w];
            g_partials[b] = s;
        }
        __threadfence();
        __syncthreads();
        if (tid == 0) atomicAdd(&g_done_x, 1);
        return;
    }

    // ======================== B role (waiters): [1152, 1216) ================
    // Wait for: all xhat (64), all edge (64), fill of rows<512 (32 blocks).
    if (tid == 0) {
        while (atomicAdd(&g_done_x, 0) < XB ||
               atomicAdd(&g_done_e, 0) < EB ||
               atomicAdd(&g_done_f0, 0) < F0)
            __nanosleep(128);
    }
    __syncthreads();
    __threadfence();   // acquire: producer writes are release-fenced

    if (tid == 0) {
        float s = 0.f;
        #pragma unroll
        for (int i = 0; i < XB; i++) s += g_partials[i];
        s_fro = s;
    }
    __syncthreads();

    int idx = (b - BID_B0) * 256 + tid;
    int nl  = g_nlist;
    int nz  = 0;
    if (idx < nl) {
        int aidx = g_list[idx];
        int cnt  = g_A[aidx];
        g_A[aidx] = 0;                         // self-clean for next replay
        int s = aidx >> 9;                     // aidx / 512
        int d = aidx & (NG0 - 1);              // aidx % 512
        const float4* ra = (const float4*)&g_Xhat[s * HDIM];
        const float4* rb = (const float4*)&g_Xhat[d * HDIM];
        float acc = 0.f;
        #pragma unroll
        for (int k = 0; k < HDIM / 4; k++) {   // same order as validated round 6
            float4 a = ra[k];
            float4 bq = rb[k];
            acc = fmaf(a.x, bq.x, acc);
            acc = fmaf(a.y, bq.y, acc);
            acc = fmaf(a.z, bq.z, acc);
            acc = fmaf(a.w, bq.w, acc);
        }
        float v = acc / s_fro - prob[0] + 0.5f * (float)cnt;
        v = fmaxf(v, 0.f);
        out[(size_t)s * NTOT + d] = v;
        nz = (v > 0.f) ? 1 : 0;
    }

#pragma unroll
    for (int off = 16; off > 0; off >>= 1) nz += __shfl_down_sync(0xffffffffu, nz, off);
    if ((tid & 31) == 0) wcount[tid >> 5] = nz;
    __syncthreads();
    if (tid == 0) {
        int t = 0;
        for (int w = 0; w < 8; w++) t += wcount[w];
        if (t) atomicAdd(&g_count, t);
        __threadfence();
        int ticket = atomicAdd(&g_done, 1);
        if (ticket == BB - 1) {                // last B block: finalize + clean
            int total_nz = *(volatile int*)&g_count;
            out[(size_t)NTOT * NTOT]     = (float)total_nz / (float)E_TOT;
            out[(size_t)NTOT * NTOT + 1] = prob[0];
            g_count   = 0;
            g_done    = 0;
            g_nlist   = 0;
            g_done_x  = 0;
            g_done_e  = 0;
            g_done_f0 = 0;
            __threadfence();
        }
    }
}

// ---------------------------------------------------------------------------
extern "C" void kernel_launch(void* const* d_in, const int* in_sizes, int n_in,
                              void* d_out, int out_size) {
    // Defensive input mapping by (distinct) element counts.
    const float* x    = nullptr;   // 524288
    const float* W0   = nullptr;   // 16384
    const float* b0   = nullptr;   // 128
    const float* prob = nullptr;   // 1
    const int*   ei   = nullptr;   // 262144
    for (int i = 0; i < n_in; i++) {
        switch (in_sizes[i]) {
            case NTOT * FDIM:  x    = (const float*)d_in[i]; break;
            case HDIM * FDIM:  W0   = (const float*)d_in[i]; break;
            case HDIM:         b0   = (const float*)d_in[i]; break;
            case 1:            prob = (const float*)d_in[i]; break;
            case 2 * E_TOT:    ei   = (const int*)d_in[i];   break;
            default: break; // batch (4096) unused: implied by i/512
        }
    }
    float* out = (float*)d_out;

    fused_kernel<<<GRID, 256>>>(x, W0, b0, ei, prob, out);
}